// round 11
// baseline (speedup 1.0000x reference)
#include <cuda_runtime.h>
#include <cuda_fp16.h>
#include <math.h>
#include <stdint.h>

#define A_    8
#define B_    4096
#define DI_   64
#define DS_   64
#define C_    32
#define H_    256
#define MW_   1024
#define MH_   1024
#define FOURH 1024

// ---------------- scratch (pre-converted fp16 operands) ----------------
__device__ __half g_Ao[8u * 4096u * 320u];        // [a][row][k]   K=320
__device__ __half g_Wo[8u * 8u * 320u * 128u];    // [a][cb8][k][jgrp*32+g*8+j7]
__device__ __half g_As[4096u * 384u];             // [row][k]      K padded to 384 (pad zero)
__device__ __half g_Ws[8u * 384u * 128u];         // [cb8][k][jgrp*32+g*8+j7] (pad zero)

// ---------------- smem layout (4-stage, BK=32, 256-thr CTA, tile 64x128) ----
#define PA_B   80        // A row pitch bytes (40 halves)
#define PB_B   272       // B row pitch bytes (136 halves)
#define SA_S   0
#define SB_S   5120
#define STAGE  13824
#define NSTAGE 4
#define STAGE_BYTES (NSTAGE * STAGE)      // 55296
// persistent epilogue operands (NOT aliased with stages)
#define EP_WOT  STAGE_BYTES               // float[32*32] = 4096
#define EP_BIAS (EP_WOT + 4096)           // float[128]
#define SMEM_BYTES (EP_BIAS + 512)        // 59904 -> 3 CTAs/SM
// per-cb aliases inside the (dead) stage region
#define EP_HS   0        // float[64*33] = 8448
#define EP_CS   8448     // float[64*33] = 8448

__device__ __forceinline__ uint32_t smem_u32(const void* p) {
    uint32_t a;
    asm("{ .reg .u64 t; cvta.to.shared.u64 t, %1; cvt.u32.u64 %0, t; }" : "=r"(a) : "l"(p));
    return a;
}
__device__ __forceinline__ uint32_t pack2h(float a, float b) {
    __half2 t = __floats2half2_rn(a, b);
    return *reinterpret_cast<uint32_t*>(&t);
}
__device__ __forceinline__ uint2 cvt4h(float4 v) {
    return make_uint2(pack2h(v.x, v.y), pack2h(v.z, v.w));
}
__device__ __forceinline__ float sigm(float x) { return 1.0f / (1.0f + __expf(-x)); }
__device__ __forceinline__ float tanh_f(float x) { return 2.0f / (1.0f + __expf(-2.0f * x)) - 1.0f; }

__device__ __forceinline__ void cp16(uint32_t saddr, const void* g) {
    asm volatile("cp.async.cg.shared.global [%0], [%1], 16;" :: "r"(saddr), "l"(g) : "memory");
}
__device__ __forceinline__ void ldm_x4(uint32_t r[4], uint32_t addr) {
    asm volatile("ldmatrix.sync.aligned.m8n8.x4.shared.b16 {%0,%1,%2,%3}, [%4];"
                 : "=r"(r[0]), "=r"(r[1]), "=r"(r[2]), "=r"(r[3]) : "r"(addr));
}
__device__ __forceinline__ void ldm_x4_t(uint32_t r[4], uint32_t addr) {
    asm volatile("ldmatrix.sync.aligned.m8n8.x4.trans.shared.b16 {%0,%1,%2,%3}, [%4];"
                 : "=r"(r[0]), "=r"(r[1]), "=r"(r[2]), "=r"(r[3]) : "r"(addr));
}
__device__ __forceinline__ void mma_f16(float d[4], const uint32_t a[4],
                                        uint32_t b0, uint32_t b1) {
    asm volatile("mma.sync.aligned.m16n8k16.row.col.f32.f16.f16.f32 "
                 "{%0,%1,%2,%3}, {%4,%5,%6,%7}, {%8,%9}, {%0,%1,%2,%3};"
                 : "+f"(d[0]), "+f"(d[1]), "+f"(d[2]), "+f"(d[3])
                 : "r"(a[0]), "r"(a[1]), "r"(a[2]), "r"(a[3]), "r"(b0), "r"(b1));
}

// ---------------------------------------------------------------------------
// prep kernels
// ---------------------------------------------------------------------------
__global__ void prepW_others_kernel(const float* __restrict__ Wk_o,
                                    const float* __restrict__ Wr_o) {
    int idx4 = blockIdx.x * blockDim.x + threadIdx.x;
    if (idx4 >= 8 * 320 * 256) return;
    int a = idx4 / (320 * 256);
    int rem = idx4 % (320 * 256);
    int k = rem / 256;
    int c = (rem % 256) * 4;
    const float* src = (k < DI_) ? (Wk_o + ((size_t)(a * DI_ + k)) * FOURH + c)
                                 : (Wr_o + ((size_t)(a * H_ + k - DI_)) * FOURH + c);
    float4 v = *(const float4*)src;
    int g = c >> 8, h = c & 255, cb = h >> 5, jloc = h & 31;
    int jgrp = jloc >> 3, j7 = jloc & 7;
    size_t dst = ((size_t)(a * 8 + cb) * 320 + k) * 128 + jgrp * 32 + g * 8 + j7;
    *(uint2*)&g_Wo[dst] = cvt4h(v);
}
__global__ void prepA_others_kernel(const float* __restrict__ x_others,
                                    const float* __restrict__ h_others) {
    int idx4 = blockIdx.x * blockDim.x + threadIdx.x;
    if (idx4 >= 8 * 4096 * 80) return;
    int a = idx4 / (4096 * 80);
    int rem = idx4 % (4096 * 80);
    int row = rem / 80;
    int k = (rem % 80) * 4;
    const float* src = (k < DI_) ? (x_others + ((size_t)a * B_ + row) * DI_ + k)
                                 : (h_others + ((size_t)a * B_ + row) * H_ + (k - DI_));
    float4 v = *(const float4*)src;
    size_t dst = ((size_t)a * B_ + row) * 320 + k;
    *(uint2*)&g_Ao[dst] = cvt4h(v);
}
__global__ void prepW_self_kernel(const float* __restrict__ Wk_self,
                                  const float* __restrict__ Wr_self) {
    int idx4 = blockIdx.x * blockDim.x + threadIdx.x;
    if (idx4 >= 352 * 256) return;
    int k = idx4 / 256;
    int c = (idx4 % 256) * 4;
    const float* src = (k < 96) ? (Wk_self + (size_t)k * FOURH + c)
                                : (Wr_self + (size_t)(k - 96) * FOURH + c);
    float4 v = *(const float4*)src;
    int g = c >> 8, h = c & 255, cb = h >> 5, jloc = h & 31;
    int jgrp = jloc >> 3, j7 = jloc & 7;
    size_t dst = ((size_t)cb * 384 + k) * 128 + jgrp * 32 + g * 8 + j7;
    *(uint2*)&g_Ws[dst] = cvt4h(v);
}
__global__ void prepA_self_kernel(const float* __restrict__ x_self,
                                  const float* __restrict__ h_self) {
    int idx4 = blockIdx.x * blockDim.x + threadIdx.x;
    if (idx4 >= 4096 * 80) return;
    int row = idx4 / 80;
    int t = idx4 % 80;
    int k = (t < 16) ? t * 4 : 96 + (t - 16) * 4;
    const float* src = (k < DS_) ? (x_self + (size_t)row * DS_ + k)
                                 : (h_self + (size_t)row * H_ + (k - 96));
    float4 v = *(const float4*)src;
    size_t dst = (size_t)row * 384 + k;
    *(uint2*)&g_As[dst] = cvt4h(v);
}
__global__ void comm_fill_kernel(const float* __restrict__ map2,
                                 const int* __restrict__ pos_self) {
    int idx = blockIdx.x * blockDim.x + threadIdx.x;
    if (idx >= 4096 * 8) return;
    int row = idx >> 3, q = idx & 7;
    int px = pos_self[(size_t)row * 2 + 0];
    int py = pos_self[(size_t)row * 2 + 1];
    float4 v = *(const float4*)(map2 + ((size_t)px * MH_ + py) * C_ + q * 4);
    size_t dst = (size_t)row * 384 + 64 + q * 4;
    *(uint2*)&g_As[dst] = cvt4h(v);
}

// ---------------------------------------------------------------------------
__global__ void copy_map_kernel(const float4* __restrict__ src,
                                float4* __restrict__ dst, int n4) {
    int i = blockIdx.x * blockDim.x + threadIdx.x;
    int stride = gridDim.x * blockDim.x;
    for (; i < n4; i += stride) dst[i] = src[i];
}
__global__ void init_out_kernel(float* __restrict__ out, const float* __restrict__ b_out) {
    int i = blockIdx.x * blockDim.x + threadIdx.x;
    if (i < B_) out[i] = b_out[0];
}

// ---------------------------------------------------------------------------
// Pipeline chunk macros (256 threads, tile 64 x 128, BK=32, single-pass fp16)
// ---------------------------------------------------------------------------
#define LOAD_CHUNK(Abase, Bbase, apitch, cc, ss) do {                                 \
    uint32_t _b = sb + (ss) * STAGE;                                                  \
    int _k0 = (cc) * 32;                                                              \
    { int _row = tid >> 2, _q = tid & 3;                                              \
      cp16(_b + SA_S + _row * PA_B + _q * 16, (Abase) + (size_t)_row * (apitch) + _k0 + _q * 8); } \
    _Pragma("unroll")                                                                 \
    for (int _i = 0; _i < 2; _i++) {                                                  \
        int _idx = tid + _i * 256;                                                    \
        int _k = _idx >> 4, _q = _idx & 15;                                           \
        cp16(_b + SB_S + _k * PB_B + _q * 16, (Bbase) + (size_t)(_k0 + _k) * 128 + _q * 8); } \
    asm volatile("cp.async.commit_group;" ::: "memory");                              \
} while (0)

// warp tile 32 rows x 32 cols; cols = 4 n8-tiles = the 4 gates for one j-oct.
#define MMA_CHUNK(ss) do {                                                            \
    uint32_t _b = sb + (ss) * STAGE;                                                  \
    _Pragma("unroll")                                                                 \
    for (int ks = 0; ks < 2; ks++) {                                                  \
        const int kk = ks * 16;                                                       \
        uint32_t ah[2][4];                                                            \
        _Pragma("unroll")                                                             \
        for (int m = 0; m < 2; m++) {                                                 \
            uint32_t aaddr = _b + SA_S + (wr2 * 32 + m * 16 + lrow) * PA_B + (kk + lk8) * 2; \
            ldm_x4(ah[m], aaddr);                                                     \
        }                                                                             \
        _Pragma("unroll")                                                             \
        for (int t = 0; t < 2; t++) {                                                 \
            uint32_t baddr = _b + SB_S + (kk + lrow) * PB_B + (n0 + t * 16 + lk8) * 2; \
            uint32_t bh[4];                                                           \
            ldm_x4_t(bh, baddr);                                                      \
            _Pragma("unroll")                                                         \
            for (int m = 0; m < 2; m++)                                               \
                _Pragma("unroll")                                                     \
                for (int o = 0; o < 2; o++)                                           \
                    mma_f16(acc[m][t * 2 + o], ah[m], bh[2 * o], bh[2 * o + 1]);      \
        }                                                                             \
    }                                                                                 \
} while (0)

// ---------------------------------------------------------------------------
// "Others": 256 thr, tile 64 rows; cb loop INSIDE the CTA (8 weight slabs of
// 128 z-cols = 4 gates x 32 h). to_map partial accumulated in registers across
// cb; ONE scatter per row at the end. grid = (rb=64, a=8).
// ---------------------------------------------------------------------------
__global__ __launch_bounds__(256, 3)
void others_mma_kernel(const float* __restrict__ c_others,
                       const float* __restrict__ b_o,
                       const float* __restrict__ W_otm,
                       const float* __restrict__ b_otm,
                       const int*   __restrict__ pos_others,
                       float*       __restrict__ map2) {
    extern __shared__ char smem[];
    const uint32_t sb = smem_u32(smem);
    const int rb = blockIdx.x, a = blockIdx.y;
    const int tid = threadIdx.x, lane = tid & 31, wid = tid >> 5;
    const int wr2 = wid >> 2, wc2 = wid & 3;
    const int n0 = wc2 * 32;
    const int r0 = rb * 64;
    const int lrow = lane & 15, lk8 = (lane >> 4) << 3;

    const __half* Ab = g_Ao + ((size_t)a * B_ + r0) * 320;

    float* Hs   = (float*)(smem + EP_HS);
    float* Cs   = (float*)(smem + EP_CS);
    float* Wot  = (float*)(smem + EP_WOT);
    float* bias = (float*)(smem + EP_BIAS);

    // to_map partial registers: thread = (channel cc, row group rgrp)
    const int cc = tid & 31, rgrp = tid >> 5;
    float accP[8];
#pragma unroll
    for (int rr = 0; rr < 8; rr++) accP[rr] = __ldg(&b_otm[cc]);

    for (int cb = 0; cb < 8; cb++) {
        const int cb0 = cb * 32;
        const __half* Bb = g_Wo + (size_t)(a * 8 + cb) * 320 * 128;

        float acc[2][4][4];
#pragma unroll
        for (int m = 0; m < 2; m++)
#pragma unroll
            for (int t = 0; t < 4; t++)
#pragma unroll
                for (int i = 0; i < 4; i++) acc[m][t][i] = 0.0f;

        LOAD_CHUNK(Ab, Bb, 320, 0, 0);
        LOAD_CHUNK(Ab, Bb, 320, 1, 1);
        LOAD_CHUNK(Ab, Bb, 320, 2, 2);

        for (int c = 0; c < 10; c++) {
            if (c < 8)       asm volatile("cp.async.wait_group 2;" ::: "memory");
            else if (c == 8) asm volatile("cp.async.wait_group 1;" ::: "memory");
            else             asm volatile("cp.async.wait_group 0;" ::: "memory");
            __syncthreads();
            MMA_CHUNK(c & 3);
            if (c + 3 < 10) LOAD_CHUNK(Ab, Bb, 320, c + 3, (c + 3) & 3);
        }
        __syncthreads();   // stages dead; Hs/Cs alias safe

        // ---- stage epilogue operands for this cb
        for (int idx = tid; idx < 64 * 32; idx += 256) {
            int row = idx >> 5, j = idx & 31;
            Cs[row * 33 + j] = c_others[((size_t)a * B_ + r0 + row) * H_ + cb0 + j];
        }
        for (int idx = tid; idx < 32 * 32; idx += 256)
            Wot[idx] = W_otm[(size_t)(cb0 + (idx >> 5)) * C_ + (idx & 31)];
        if (tid < 128) bias[tid] = b_o[a * FOURH + (tid >> 5) * 256 + cb0 + (tid & 31)];
        __syncthreads();

        // ---- gates -> Hs (each thread owns all 4 gates of its jloc)
        {
            const int gr = lane >> 2, cq = lane & 3;
#pragma unroll
            for (int m = 0; m < 2; m++)
#pragma unroll
                for (int rh = 0; rh < 2; rh++) {
                    int row = wr2 * 32 + m * 16 + rh * 8 + gr;
#pragma unroll
                    for (int p = 0; p < 2; p++) {
                        int j = wc2 * 8 + cq * 2 + p;
                        float zi = acc[m][0][rh * 2 + p] + bias[j];
                        float zf = acc[m][1][rh * 2 + p] + bias[32 + j];
                        float zg = acc[m][2][rh * 2 + p] + bias[64 + j];
                        float zo = acc[m][3][rh * 2 + p] + bias[96 + j];
                        float cp = Cs[row * 33 + j];
                        float c2 = sigm(zf) * cp + sigm(zi) * tanh_f(zg);
                        Hs[row * 33 + j] = sigm(zo) * tanh_f(c2);
                    }
                }
        }
        __syncthreads();

        // ---- to_map partial accumulate (registers, across cb)
#pragma unroll
        for (int rr = 0; rr < 8; rr++) {
            int row = rgrp * 8 + rr;
            float p = accP[rr];
#pragma unroll 8
            for (int j = 0; j < 32; j++) p += Hs[row * 33 + j] * Wot[j * 32 + cc];
            accP[rr] = p;
        }
        __syncthreads();   // Hs dead before next cb's stage loads
    }

    // ---- single scatter per row
#pragma unroll
    for (int rr = 0; rr < 8; rr++) {
        int rg = r0 + rgrp * 8 + rr;
        int px = pos_others[((size_t)a * B_ + rg) * 2 + 0];
        int py = pos_others[((size_t)a * B_ + rg) * 2 + 1];
        atomicAdd(map2 + ((size_t)px * MH_ + py) * C_ + cc, accP[rr]);
    }
}

// ---------------------------------------------------------------------------
// "Self": K=384 (pad), 12 chunks, 4-stage pipeline. grid = (cb=8, rb=64).
// ---------------------------------------------------------------------------
__global__ __launch_bounds__(256, 3)
void self_mma_kernel(const float* __restrict__ c_self,
                     const float* __restrict__ b_self,
                     const float* __restrict__ W_out,
                     float*       __restrict__ out) {
    extern __shared__ char smem[];
    const uint32_t sb = smem_u32(smem);
    const int cb = blockIdx.x, rb = blockIdx.y;
    const int tid = threadIdx.x, lane = tid & 31, wid = tid >> 5;
    const int wr2 = wid >> 2, wc2 = wid & 3;
    const int n0 = wc2 * 32;
    const int r0 = rb * 64, cb0 = cb * 32;
    const int lrow = lane & 15, lk8 = (lane >> 4) << 3;

    const __half* Ab = g_As + (size_t)r0 * 384;
    const __half* Bb = g_Ws + (size_t)cb * 384 * 128;

    float* Hs   = (float*)(smem + EP_HS);
    float* Cs   = (float*)(smem + EP_CS);
    float* bias = (float*)(smem + EP_WOT);           // reuse region
    float* wv   = (float*)(smem + EP_BIAS);

    float acc[2][4][4];
#pragma unroll
    for (int m = 0; m < 2; m++)
#pragma unroll
        for (int t = 0; t < 4; t++)
#pragma unroll
            for (int i = 0; i < 4; i++) acc[m][t][i] = 0.0f;

    LOAD_CHUNK(Ab, Bb, 384, 0, 0);
    LOAD_CHUNK(Ab, Bb, 384, 1, 1);
    LOAD_CHUNK(Ab, Bb, 384, 2, 2);

    for (int c = 0; c < 12; c++) {
        if (c < 10)       asm volatile("cp.async.wait_group 2;" ::: "memory");
        else if (c == 10) asm volatile("cp.async.wait_group 1;" ::: "memory");
        else              asm volatile("cp.async.wait_group 0;" ::: "memory");
        __syncthreads();
        MMA_CHUNK(c & 3);
        if (c + 3 < 12) LOAD_CHUNK(Ab, Bb, 384, c + 3, (c + 3) & 3);
    }
    __syncthreads();

    for (int idx = tid; idx < 64 * 32; idx += 256) {
        int row = idx >> 5, j = idx & 31;
        Cs[row * 33 + j] = c_self[(size_t)(r0 + row) * H_ + cb0 + j];
    }
    if (tid < 128)      bias[tid] = b_self[(tid >> 5) * 256 + cb0 + (tid & 31)];
    else if (tid < 160) wv[tid - 128] = W_out[cb0 + tid - 128];
    __syncthreads();

    {
        const int gr = lane >> 2, cq = lane & 3;
#pragma unroll
        for (int m = 0; m < 2; m++)
#pragma unroll
            for (int rh = 0; rh < 2; rh++) {
                int row = wr2 * 32 + m * 16 + rh * 8 + gr;
#pragma unroll
                for (int p = 0; p < 2; p++) {
                    int j = wc2 * 8 + cq * 2 + p;
                    float zi = acc[m][0][rh * 2 + p] + bias[j];
                    float zf = acc[m][1][rh * 2 + p] + bias[32 + j];
                    float zg = acc[m][2][rh * 2 + p] + bias[64 + j];
                    float zo = acc[m][3][rh * 2 + p] + bias[96 + j];
                    float cp = Cs[row * 33 + j];
                    float c2 = sigm(zf) * cp + sigm(zi) * tanh_f(zg);
                    Hs[row * 33 + j] = sigm(zo) * tanh_f(c2);
                }
            }
    }
    __syncthreads();

    if (tid < 64) {
        int row = tid;
        float p = 0.0f;
#pragma unroll 8
        for (int j = 0; j < 32; j++) p += Hs[row * 33 + j] * wv[j];
        atomicAdd(&out[r0 + row], p);
    }
}

// ---------------------------------------------------------------------------
extern "C" void kernel_launch(void* const* d_in, const int* in_sizes, int n_in,
                              void* d_out, int out_size) {
    const float* x_self     = (const float*)d_in[0];
    const float* x_others   = (const float*)d_in[1];
    const float* blurmap    = (const float*)d_in[2];
    const float* h_self     = (const float*)d_in[3];
    const float* c_self     = (const float*)d_in[4];
    const float* h_others   = (const float*)d_in[5];
    const float* c_others   = (const float*)d_in[6];
    const float* Wk_self    = (const float*)d_in[7];
    const float* Wr_self    = (const float*)d_in[8];
    const float* b_self     = (const float*)d_in[9];
    const float* Wk_o       = (const float*)d_in[10];
    const float* Wr_o       = (const float*)d_in[11];
    const float* b_o        = (const float*)d_in[12];
    const float* W_otm      = (const float*)d_in[13];
    const float* b_otm      = (const float*)d_in[14];
    const float* W_out      = (const float*)d_in[15];
    const float* b_out      = (const float*)d_in[16];
    const int*   pos_others = (const int*)d_in[17];
    const int*   pos_self   = (const int*)d_in[18];

    float* out  = (float*)d_out;
    float* map2 = out + B_;

    static int smem_set = 0;
    if (!smem_set) {
        cudaFuncSetAttribute(others_mma_kernel, cudaFuncAttributeMaxDynamicSharedMemorySize, SMEM_BYTES);
        cudaFuncSetAttribute(self_mma_kernel,   cudaFuncAttributeMaxDynamicSharedMemorySize, SMEM_BYTES);
        smem_set = 1;
    }

    const int n4 = (MW_ * MH_ * C_) / 4;

    // Order keeps others_mma_kernel as the 4th launch (ncu -s 5 -c 1 target).
    prepW_others_kernel<<<(8 * 320 * 256 + 255) / 256, 256>>>(Wk_o, Wr_o);          // 1
    prepA_others_kernel<<<(8 * 4096 * 80 + 255) / 256, 256>>>(x_others, h_others);  // 2
    copy_map_kernel<<<8192, 256>>>((const float4*)blurmap, (float4*)map2, n4);      // 3
    others_mma_kernel<<<dim3(64, 8), 256, SMEM_BYTES>>>(                            // 4
        c_others, b_o, W_otm, b_otm, pos_others, map2);

    prepW_self_kernel<<<(352 * 256 + 255) / 256, 256>>>(Wk_self, Wr_self);          // 5
    prepA_self_kernel<<<(4096 * 80 + 255) / 256, 256>>>(x_self, h_self);            // 6
    comm_fill_kernel<<<(4096 * 8 + 255) / 256, 256>>>(map2, pos_self);              // 7
    init_out_kernel<<<(B_ + 255) / 256, 256>>>(out, b_out);                         // 8
    self_mma_kernel<<<dim3(8, 64), 256, SMEM_BYTES>>>(                              // 9
        c_self, b_self, W_out, out);
}

// round 16
// speedup vs baseline: 1.2122x; 1.2122x over previous
#include <cuda_runtime.h>
#include <cuda_fp16.h>
#include <math.h>
#include <stdint.h>

#define A_    8
#define B_    4096
#define DI_   64
#define DS_   64
#define C_    32
#define H_    256
#define MW_   1024
#define MH_   1024
#define FOURH 1024

// ---------------- scratch (pre-converted fp16 operands) ----------------
__device__ __half g_Ao[8u * 4096u * 320u];        // [a][row][k]   K=320
__device__ __half g_Wo[8u * 8u * 320u * 128u];    // [a][cb8][k][jgrp*32+g*8+j7]
__device__ __half g_As[4096u * 384u];             // [row][k]      K padded to 384 (pad zero)
__device__ __half g_Ws[8u * 384u * 128u];         // [cb8][k][jgrp*32+g*8+j7] (pad zero)

// ---------------- smem layout (4-stage, BK=32, 256-thr CTA, tile 64x128) ----
#define PA_B   80        // A row pitch bytes (40 halves)
#define PB_B   272       // B row pitch bytes (136 halves)
#define SA_S   0
#define SB_S   5120
#define STAGE  13824
#define NSTAGE 4
#define STAGE_BYTES (NSTAGE * STAGE)      // 55296
// persistent epilogue operands (NOT aliased with stages)
#define EP_WOT  STAGE_BYTES               // float[32*32] = 4096
#define EP_BIAS (EP_WOT + 4096)           // float[128]
#define SMEM_BYTES (EP_BIAS + 512)        // 59904 -> 3 CTAs/SM
// per-cb aliases inside the (dead) stage region
#define EP_HS   0        // float[64*33] = 8448
#define EP_CS   8448     // float[64*33] = 8448

__device__ __forceinline__ uint32_t smem_u32(const void* p) {
    uint32_t a;
    asm("{ .reg .u64 t; cvta.to.shared.u64 t, %1; cvt.u32.u64 %0, t; }" : "=r"(a) : "l"(p));
    return a;
}
__device__ __forceinline__ uint32_t pack2h(float a, float b) {
    __half2 t = __floats2half2_rn(a, b);
    return *reinterpret_cast<uint32_t*>(&t);
}
__device__ __forceinline__ uint2 cvt4h(float4 v) {
    return make_uint2(pack2h(v.x, v.y), pack2h(v.z, v.w));
}
__device__ __forceinline__ float sigm(float x) { return 1.0f / (1.0f + __expf(-x)); }
__device__ __forceinline__ float tanh_f(float x) { return 2.0f / (1.0f + __expf(-2.0f * x)) - 1.0f; }

__device__ __forceinline__ void cp16(uint32_t saddr, const void* g) {
    asm volatile("cp.async.cg.shared.global [%0], [%1], 16;" :: "r"(saddr), "l"(g) : "memory");
}
__device__ __forceinline__ void ldm_x4(uint32_t r[4], uint32_t addr) {
    asm volatile("ldmatrix.sync.aligned.m8n8.x4.shared.b16 {%0,%1,%2,%3}, [%4];"
                 : "=r"(r[0]), "=r"(r[1]), "=r"(r[2]), "=r"(r[3]) : "r"(addr));
}
__device__ __forceinline__ void ldm_x4_t(uint32_t r[4], uint32_t addr) {
    asm volatile("ldmatrix.sync.aligned.m8n8.x4.trans.shared.b16 {%0,%1,%2,%3}, [%4];"
                 : "=r"(r[0]), "=r"(r[1]), "=r"(r[2]), "=r"(r[3]) : "r"(addr));
}
__device__ __forceinline__ void mma_f16(float d[4], const uint32_t a[4],
                                        uint32_t b0, uint32_t b1) {
    asm volatile("mma.sync.aligned.m16n8k16.row.col.f32.f16.f16.f32 "
                 "{%0,%1,%2,%3}, {%4,%5,%6,%7}, {%8,%9}, {%0,%1,%2,%3};"
                 : "+f"(d[0]), "+f"(d[1]), "+f"(d[2]), "+f"(d[3])
                 : "r"(a[0]), "r"(a[1]), "r"(a[2]), "r"(a[3]), "r"(b0), "r"(b1));
}

// ---------------------------------------------------------------------------
// prep kernels
// ---------------------------------------------------------------------------
__global__ void prepW_others_kernel(const float* __restrict__ Wk_o,
                                    const float* __restrict__ Wr_o) {
    int idx4 = blockIdx.x * blockDim.x + threadIdx.x;
    if (idx4 >= 8 * 320 * 256) return;
    int a = idx4 / (320 * 256);
    int rem = idx4 % (320 * 256);
    int k = rem / 256;
    int c = (rem % 256) * 4;
    const float* src = (k < DI_) ? (Wk_o + ((size_t)(a * DI_ + k)) * FOURH + c)
                                 : (Wr_o + ((size_t)(a * H_ + k - DI_)) * FOURH + c);
    float4 v = *(const float4*)src;
    int g = c >> 8, h = c & 255, cb = h >> 5, jloc = h & 31;
    int jgrp = jloc >> 3, j7 = jloc & 7;
    size_t dst = ((size_t)(a * 8 + cb) * 320 + k) * 128 + jgrp * 32 + g * 8 + j7;
    *(uint2*)&g_Wo[dst] = cvt4h(v);
}
__global__ void prepA_others_kernel(const float* __restrict__ x_others,
                                    const float* __restrict__ h_others) {
    int idx4 = blockIdx.x * blockDim.x + threadIdx.x;
    if (idx4 >= 8 * 4096 * 80) return;
    int a = idx4 / (4096 * 80);
    int rem = idx4 % (4096 * 80);
    int row = rem / 80;
    int k = (rem % 80) * 4;
    const float* src = (k < DI_) ? (x_others + ((size_t)a * B_ + row) * DI_ + k)
                                 : (h_others + ((size_t)a * B_ + row) * H_ + (k - DI_));
    float4 v = *(const float4*)src;
    size_t dst = ((size_t)a * B_ + row) * 320 + k;
    *(uint2*)&g_Ao[dst] = cvt4h(v);
}
__global__ void prepW_self_kernel(const float* __restrict__ Wk_self,
                                  const float* __restrict__ Wr_self) {
    int idx4 = blockIdx.x * blockDim.x + threadIdx.x;
    if (idx4 >= 352 * 256) return;
    int k = idx4 / 256;
    int c = (idx4 % 256) * 4;
    const float* src = (k < 96) ? (Wk_self + (size_t)k * FOURH + c)
                                : (Wr_self + (size_t)(k - 96) * FOURH + c);
    float4 v = *(const float4*)src;
    int g = c >> 8, h = c & 255, cb = h >> 5, jloc = h & 31;
    int jgrp = jloc >> 3, j7 = jloc & 7;
    size_t dst = ((size_t)cb * 384 + k) * 128 + jgrp * 32 + g * 8 + j7;
    *(uint2*)&g_Ws[dst] = cvt4h(v);
}
__global__ void prepA_self_kernel(const float* __restrict__ x_self,
                                  const float* __restrict__ h_self) {
    int idx4 = blockIdx.x * blockDim.x + threadIdx.x;
    if (idx4 >= 4096 * 80) return;
    int row = idx4 / 80;
    int t = idx4 % 80;
    int k = (t < 16) ? t * 4 : 96 + (t - 16) * 4;
    const float* src = (k < DS_) ? (x_self + (size_t)row * DS_ + k)
                                 : (h_self + (size_t)row * H_ + (k - 96));
    float4 v = *(const float4*)src;
    size_t dst = (size_t)row * 384 + k;
    *(uint2*)&g_As[dst] = cvt4h(v);
}
__global__ void comm_fill_kernel(const float* __restrict__ map2,
                                 const int* __restrict__ pos_self) {
    int idx = blockIdx.x * blockDim.x + threadIdx.x;
    if (idx >= 4096 * 8) return;
    int row = idx >> 3, q = idx & 7;
    int px = pos_self[(size_t)row * 2 + 0];
    int py = pos_self[(size_t)row * 2 + 1];
    float4 v = *(const float4*)(map2 + ((size_t)px * MH_ + py) * C_ + q * 4);
    size_t dst = (size_t)row * 384 + 64 + q * 4;
    *(uint2*)&g_As[dst] = cvt4h(v);
}

// ---------------------------------------------------------------------------
__global__ void copy_map_kernel(const float4* __restrict__ src,
                                float4* __restrict__ dst, int n4) {
    int i = blockIdx.x * blockDim.x + threadIdx.x;
    int stride = gridDim.x * blockDim.x;
    for (; i < n4; i += stride) dst[i] = src[i];
}
__global__ void init_out_kernel(float* __restrict__ out, const float* __restrict__ b_out) {
    int i = blockIdx.x * blockDim.x + threadIdx.x;
    if (i < B_) out[i] = b_out[0];
}

// ---------------------------------------------------------------------------
// Pipeline chunk macros (256 threads, tile 64 x 128, BK=32, single-pass fp16)
// ---------------------------------------------------------------------------
#define LOAD_CHUNK(Abase, Bbase, apitch, cc, ss) do {                                 \
    uint32_t _b = sb + (ss) * STAGE;                                                  \
    int _k0 = (cc) * 32;                                                              \
    { int _row = tid >> 2, _q = tid & 3;                                              \
      cp16(_b + SA_S + _row * PA_B + _q * 16, (Abase) + (size_t)_row * (apitch) + _k0 + _q * 8); } \
    _Pragma("unroll")                                                                 \
    for (int _i = 0; _i < 2; _i++) {                                                  \
        int _idx = tid + _i * 256;                                                    \
        int _k = _idx >> 4, _q = _idx & 15;                                           \
        cp16(_b + SB_S + _k * PB_B + _q * 16, (Bbase) + (size_t)(_k0 + _k) * 128 + _q * 8); } \
    asm volatile("cp.async.commit_group;" ::: "memory");                              \
} while (0)

// warp tile 32 rows x 32 cols; cols = 4 n8-tiles = the 4 gates for one j-oct.
#define MMA_CHUNK(ss) do {                                                            \
    uint32_t _b = sb + (ss) * STAGE;                                                  \
    _Pragma("unroll")                                                                 \
    for (int ks = 0; ks < 2; ks++) {                                                  \
        const int kk = ks * 16;                                                       \
        uint32_t ah[2][4];                                                            \
        _Pragma("unroll")                                                             \
        for (int m = 0; m < 2; m++) {                                                 \
            uint32_t aaddr = _b + SA_S + (wr2 * 32 + m * 16 + lrow) * PA_B + (kk + lk8) * 2; \
            ldm_x4(ah[m], aaddr);                                                     \
        }                                                                             \
        _Pragma("unroll")                                                             \
        for (int t = 0; t < 2; t++) {                                                 \
            uint32_t baddr = _b + SB_S + (kk + lrow) * PB_B + (n0 + t * 16 + lk8) * 2; \
            uint32_t bh[4];                                                           \
            ldm_x4_t(bh, baddr);                                                      \
            _Pragma("unroll")                                                         \
            for (int m = 0; m < 2; m++)                                               \
                _Pragma("unroll")                                                     \
                for (int o = 0; o < 2; o++)                                           \
                    mma_f16(acc[m][t * 2 + o], ah[m], bh[2 * o], bh[2 * o + 1]);      \
        }                                                                             \
    }                                                                                 \
} while (0)

// ---------------------------------------------------------------------------
// "Others": 256 thr, tile 64 rows; TWO weight slabs per CTA (cb = 2*cb2 + i).
// to_map partial accumulated in registers across the 2 slabs; ONE scatter.
// grid = (cb2=4, rb=64, a=8) = 2048 CTAs (~4.6 waves at 3 CTAs/SM).
// ---------------------------------------------------------------------------
__global__ __launch_bounds__(256, 3)
void others_mma_kernel(const float* __restrict__ c_others,
                       const float* __restrict__ b_o,
                       const float* __restrict__ W_otm,
                       const float* __restrict__ b_otm,
                       const int*   __restrict__ pos_others,
                       float*       __restrict__ map2) {
    extern __shared__ char smem[];
    const uint32_t sb = smem_u32(smem);
    const int cb2 = blockIdx.x, rb = blockIdx.y, a = blockIdx.z;
    const int tid = threadIdx.x, lane = tid & 31, wid = tid >> 5;
    const int wr2 = wid >> 2, wc2 = wid & 3;
    const int n0 = wc2 * 32;
    const int r0 = rb * 64;
    const int lrow = lane & 15, lk8 = (lane >> 4) << 3;

    const __half* Ab = g_Ao + ((size_t)a * B_ + r0) * 320;

    float* Hs   = (float*)(smem + EP_HS);
    float* Cs   = (float*)(smem + EP_CS);
    float* Wot  = (float*)(smem + EP_WOT);
    float* bias = (float*)(smem + EP_BIAS);

    // to_map partial registers: thread = (channel cc, row group rgrp)
    const int cc = tid & 31, rgrp = tid >> 5;
    float accP[8];
#pragma unroll
    for (int rr = 0; rr < 8; rr++) accP[rr] = (cb2 == 0) ? __ldg(&b_otm[cc]) : 0.0f;

    for (int ci = 0; ci < 2; ci++) {
        const int cb  = cb2 * 2 + ci;
        const int cb0 = cb * 32;
        const __half* Bb = g_Wo + (size_t)(a * 8 + cb) * 320 * 128;

        float acc[2][4][4];
#pragma unroll
        for (int m = 0; m < 2; m++)
#pragma unroll
            for (int t = 0; t < 4; t++)
#pragma unroll
                for (int i = 0; i < 4; i++) acc[m][t][i] = 0.0f;

        LOAD_CHUNK(Ab, Bb, 320, 0, 0);
        LOAD_CHUNK(Ab, Bb, 320, 1, 1);
        LOAD_CHUNK(Ab, Bb, 320, 2, 2);

        for (int c = 0; c < 10; c++) {
            if (c < 8)       asm volatile("cp.async.wait_group 2;" ::: "memory");
            else if (c == 8) asm volatile("cp.async.wait_group 1;" ::: "memory");
            else             asm volatile("cp.async.wait_group 0;" ::: "memory");
            __syncthreads();
            MMA_CHUNK(c & 3);
            if (c + 3 < 10) LOAD_CHUNK(Ab, Bb, 320, c + 3, (c + 3) & 3);
        }
        __syncthreads();   // stages dead; Hs/Cs alias safe

        // ---- stage epilogue operands for this cb
        for (int idx = tid; idx < 64 * 32; idx += 256) {
            int row = idx >> 5, j = idx & 31;
            Cs[row * 33 + j] = c_others[((size_t)a * B_ + r0 + row) * H_ + cb0 + j];
        }
        for (int idx = tid; idx < 32 * 32; idx += 256)
            Wot[idx] = W_otm[(size_t)(cb0 + (idx >> 5)) * C_ + (idx & 31)];
        if (tid < 128) bias[tid] = b_o[a * FOURH + (tid >> 5) * 256 + cb0 + (tid & 31)];
        __syncthreads();

        // ---- gates -> Hs (each thread owns all 4 gates of its jloc)
        {
            const int gr = lane >> 2, cq = lane & 3;
#pragma unroll
            for (int m = 0; m < 2; m++)
#pragma unroll
                for (int rh = 0; rh < 2; rh++) {
                    int row = wr2 * 32 + m * 16 + rh * 8 + gr;
#pragma unroll
                    for (int p = 0; p < 2; p++) {
                        int j = wc2 * 8 + cq * 2 + p;
                        float zi = acc[m][0][rh * 2 + p] + bias[j];
                        float zf = acc[m][1][rh * 2 + p] + bias[32 + j];
                        float zg = acc[m][2][rh * 2 + p] + bias[64 + j];
                        float zo = acc[m][3][rh * 2 + p] + bias[96 + j];
                        float cp = Cs[row * 33 + j];
                        float c2 = sigm(zf) * cp + sigm(zi) * tanh_f(zg);
                        Hs[row * 33 + j] = sigm(zo) * tanh_f(c2);
                    }
                }
        }
        __syncthreads();

        // ---- to_map partial accumulate (registers, across the 2 slabs)
#pragma unroll
        for (int rr = 0; rr < 8; rr++) {
            int row = rgrp * 8 + rr;
            float p = accP[rr];
#pragma unroll 8
            for (int j = 0; j < 32; j++) p += Hs[row * 33 + j] * Wot[j * 32 + cc];
            accP[rr] = p;
        }
        __syncthreads();   // Hs dead before next slab's stage loads
    }

    // ---- single scatter per row
#pragma unroll
    for (int rr = 0; rr < 8; rr++) {
        int rg = r0 + rgrp * 8 + rr;
        int px = pos_others[((size_t)a * B_ + rg) * 2 + 0];
        int py = pos_others[((size_t)a * B_ + rg) * 2 + 1];
        atomicAdd(map2 + ((size_t)px * MH_ + py) * C_ + cc, accP[rr]);
    }
}

// ---------------------------------------------------------------------------
// "Self": K=384 (pad), 12 chunks, 4-stage pipeline. grid = (cb=8, rb=64).
// ---------------------------------------------------------------------------
__global__ __launch_bounds__(256, 3)
void self_mma_kernel(const float* __restrict__ c_self,
                     const float* __restrict__ b_self,
                     const float* __restrict__ W_out,
                     float*       __restrict__ out) {
    extern __shared__ char smem[];
    const uint32_t sb = smem_u32(smem);
    const int cb = blockIdx.x, rb = blockIdx.y;
    const int tid = threadIdx.x, lane = tid & 31, wid = tid >> 5;
    const int wr2 = wid >> 2, wc2 = wid & 3;
    const int n0 = wc2 * 32;
    const int r0 = rb * 64, cb0 = cb * 32;
    const int lrow = lane & 15, lk8 = (lane >> 4) << 3;

    const __half* Ab = g_As + (size_t)r0 * 384;
    const __half* Bb = g_Ws + (size_t)cb * 384 * 128;

    float* Hs   = (float*)(smem + EP_HS);
    float* Cs   = (float*)(smem + EP_CS);
    float* bias = (float*)(smem + EP_WOT);           // reuse region
    float* wv   = (float*)(smem + EP_BIAS);

    float acc[2][4][4];
#pragma unroll
    for (int m = 0; m < 2; m++)
#pragma unroll
        for (int t = 0; t < 4; t++)
#pragma unroll
            for (int i = 0; i < 4; i++) acc[m][t][i] = 0.0f;

    LOAD_CHUNK(Ab, Bb, 384, 0, 0);
    LOAD_CHUNK(Ab, Bb, 384, 1, 1);
    LOAD_CHUNK(Ab, Bb, 384, 2, 2);

    for (int c = 0; c < 12; c++) {
        if (c < 10)       asm volatile("cp.async.wait_group 2;" ::: "memory");
        else if (c == 10) asm volatile("cp.async.wait_group 1;" ::: "memory");
        else              asm volatile("cp.async.wait_group 0;" ::: "memory");
        __syncthreads();
        MMA_CHUNK(c & 3);
        if (c + 3 < 12) LOAD_CHUNK(Ab, Bb, 384, c + 3, (c + 3) & 3);
    }
    __syncthreads();

    for (int idx = tid; idx < 64 * 32; idx += 256) {
        int row = idx >> 5, j = idx & 31;
        Cs[row * 33 + j] = c_self[(size_t)(r0 + row) * H_ + cb0 + j];
    }
    if (tid < 128)      bias[tid] = b_self[(tid >> 5) * 256 + cb0 + (tid & 31)];
    else if (tid < 160) wv[tid - 128] = W_out[cb0 + tid - 128];
    __syncthreads();

    {
        const int gr = lane >> 2, cq = lane & 3;
#pragma unroll
        for (int m = 0; m < 2; m++)
#pragma unroll
            for (int rh = 0; rh < 2; rh++) {
                int row = wr2 * 32 + m * 16 + rh * 8 + gr;
#pragma unroll
                for (int p = 0; p < 2; p++) {
                    int j = wc2 * 8 + cq * 2 + p;
                    float zi = acc[m][0][rh * 2 + p] + bias[j];
                    float zf = acc[m][1][rh * 2 + p] + bias[32 + j];
                    float zg = acc[m][2][rh * 2 + p] + bias[64 + j];
                    float zo = acc[m][3][rh * 2 + p] + bias[96 + j];
                    float cp = Cs[row * 33 + j];
                    float c2 = sigm(zf) * cp + sigm(zi) * tanh_f(zg);
                    Hs[row * 33 + j] = sigm(zo) * tanh_f(c2);
                }
            }
    }
    __syncthreads();

    if (tid < 64) {
        int row = tid;
        float p = 0.0f;
#pragma unroll 8
        for (int j = 0; j < 32; j++) p += Hs[row * 33 + j] * wv[j];
        atomicAdd(&out[r0 + row], p);
    }
}

// ---------------------------------------------------------------------------
extern "C" void kernel_launch(void* const* d_in, const int* in_sizes, int n_in,
                              void* d_out, int out_size) {
    const float* x_self     = (const float*)d_in[0];
    const float* x_others   = (const float*)d_in[1];
    const float* blurmap    = (const float*)d_in[2];
    const float* h_self     = (const float*)d_in[3];
    const float* c_self     = (const float*)d_in[4];
    const float* h_others   = (const float*)d_in[5];
    const float* c_others   = (const float*)d_in[6];
    const float* Wk_self    = (const float*)d_in[7];
    const float* Wr_self    = (const float*)d_in[8];
    const float* b_self     = (const float*)d_in[9];
    const float* Wk_o       = (const float*)d_in[10];
    const float* Wr_o       = (const float*)d_in[11];
    const float* b_o        = (const float*)d_in[12];
    const float* W_otm      = (const float*)d_in[13];
    const float* b_otm      = (const float*)d_in[14];
    const float* W_out      = (const float*)d_in[15];
    const float* b_out      = (const float*)d_in[16];
    const int*   pos_others = (const int*)d_in[17];
    const int*   pos_self   = (const int*)d_in[18];

    float* out  = (float*)d_out;
    float* map2 = out + B_;

    static int smem_set = 0;
    if (!smem_set) {
        cudaFuncSetAttribute(others_mma_kernel, cudaFuncAttributeMaxDynamicSharedMemorySize, SMEM_BYTES);
        cudaFuncSetAttribute(self_mma_kernel,   cudaFuncAttributeMaxDynamicSharedMemorySize, SMEM_BYTES);
        smem_set = 1;
    }

    const int n4 = (MW_ * MH_ * C_) / 4;

    // Order keeps others_mma_kernel as the 4th launch (ncu -s 5 -c 1 target).
    prepW_others_kernel<<<(8 * 320 * 256 + 255) / 256, 256>>>(Wk_o, Wr_o);          // 1
    prepA_others_kernel<<<(8 * 4096 * 80 + 255) / 256, 256>>>(x_others, h_others);  // 2
    copy_map_kernel<<<8192, 256>>>((const float4*)blurmap, (float4*)map2, n4);      // 3
    others_mma_kernel<<<dim3(4, 64, 8), 256, SMEM_BYTES>>>(                         // 4
        c_others, b_o, W_otm, b_otm, pos_others, map2);

    prepW_self_kernel<<<(352 * 256 + 255) / 256, 256>>>(Wk_self, Wr_self);          // 5
    prepA_self_kernel<<<(4096 * 80 + 255) / 256, 256>>>(x_self, h_self);            // 6
    comm_fill_kernel<<<(4096 * 8 + 255) / 256, 256>>>(map2, pos_self);              // 7
    init_out_kernel<<<(B_ + 255) / 256, 256>>>(out, b_out);                         // 8
    self_mma_kernel<<<dim3(8, 64), 256, SMEM_BYTES>>>(                              // 9
        c_self, b_self, W_out, out);
}